// round 1
// baseline (speedup 1.0000x reference)
#include <cuda_runtime.h>

#define NN 50000
#define EE 1600000

// ---- scratch (static device globals; no allocation allowed) ----
__device__ float g_xp[NN * 128];     // node projections [N,128]
__device__ float g_as[NN * 4];       // per-node source attn scalar [N,H]
__device__ float g_at[NN * 4];       // per-node target attn scalar [N,H]
__device__ float g_ae[EE * 4];       // per-edge attn scalar [E,H] (original order)
__device__ float g_ab[EE * 4];       // sorted a_s[src]+a_e per edge [E,H]
__device__ int   g_srcs[EE];         // sorted source ids
__device__ int   g_deg[NN];
__device__ int   g_off[NN + 1];
__device__ int   g_cur[NN];
__device__ float g_ve[64];           // folded edge vectors v_e[h][k], h<4,k<16

// ---------------------------------------------------------------
// K0: fold W_edge with w_e:  v_e[h,k] = sum_f w_e[f] * W_edge[h*32+f, k]
__global__ void k_fold(const float* __restrict__ W_edge,
                       const float* __restrict__ w_e) {
    int t = threadIdx.x;          // 64 threads
    int h = t >> 4, k = t & 15;
    float s = 0.f;
#pragma unroll
    for (int f = 0; f < 32; f++) s += w_e[f] * W_edge[(h * 32 + f) * 16 + k];
    g_ve[t] = s;
}

// K0b: zero degree histogram
__global__ void k_zero() {
    int i = blockIdx.x * blockDim.x + threadIdx.x;
    if (i < NN) g_deg[i] = 0;
}

// ---------------------------------------------------------------
// K1: node projections. Threads 0..127 compute xp row (x@W_lin^T),
//     threads 128..255 compute residual row (x@W_res^T + bias) into out.
//     Then a_s / a_t per head from xp.
__global__ __launch_bounds__(256) void k_node(
    const float* __restrict__ x,
    const float* __restrict__ W_lin, const float* __restrict__ W_res,
    const float* __restrict__ bias,
    const float* __restrict__ w_s, const float* __restrict__ b_s,
    const float* __restrict__ w_t, const float* __restrict__ b_t,
    float* __restrict__ out) {
    __shared__ float4 sx[16];
    __shared__ float  sxp[128];
    __shared__ float  sws[32], swt[32];

    int t = threadIdx.x;
    // weight row into registers (re-used across all nodes of this block)
    float w[64];
    const float4* Wrow4 = (t < 128)
        ? ((const float4*)W_lin + t * 16)
        : ((const float4*)W_res + (t - 128) * 16);
#pragma unroll
    for (int k = 0; k < 16; k++) {
        float4 v = Wrow4[k];
        w[4 * k] = v.x; w[4 * k + 1] = v.y; w[4 * k + 2] = v.z; w[4 * k + 3] = v.w;
    }
    float bval = (t >= 128) ? bias[t - 128] : 0.f;
    if (t < 32) sws[t] = w_s[t];
    else if (t < 64) swt[t - 32] = w_t[t - 32];
    float bsv = b_s[0], btv = b_t[0];

    for (int n = blockIdx.x; n < NN; n += gridDim.x) {
        __syncthreads();
        if (t < 16) sx[t] = ((const float4*)x)[n * 16 + t];
        __syncthreads();
        float acc = 0.f;
#pragma unroll
        for (int k = 0; k < 16; k++) {
            float4 xv = sx[k];
            acc += w[4 * k] * xv.x + w[4 * k + 1] * xv.y
                 + w[4 * k + 2] * xv.z + w[4 * k + 3] * xv.w;
        }
        if (t < 128) { g_xp[n * 128 + t] = acc; sxp[t] = acc; }
        else          out[n * 128 + (t - 128)] = acc + bval;
        __syncthreads();
        if (t < 8) {
            int h = t & 3;
            const float* wv = (t < 4) ? sws : swt;
            float s = 0.f;
#pragma unroll
            for (int f = 0; f < 32; f++) s += sxp[h * 32 + f] * wv[f];
            if (t < 4) g_as[n * 4 + h] = s + bsv;
            else       g_at[n * 4 + h] = s + btv;
        }
    }
}

// ---------------------------------------------------------------
// K2: per-edge a_e = edge_attr . v_e + b_e, plus degree histogram of dst
__global__ __launch_bounds__(256) void k_edge(
    const float* __restrict__ ea, const int* __restrict__ ei,
    const float* __restrict__ b_e) {
    __shared__ float sve[64];
    if (threadIdx.x < 64) sve[threadIdx.x] = g_ve[threadIdx.x];
    __syncthreads();
    float bev = b_e[0];
    int e = blockIdx.x * blockDim.x + threadIdx.x;
    if (e >= EE) return;

    float av[16];
    const float4* p = (const float4*)ea + e * 4;
#pragma unroll
    for (int i = 0; i < 4; i++) {
        float4 q = p[i];
        av[4 * i] = q.x; av[4 * i + 1] = q.y; av[4 * i + 2] = q.z; av[4 * i + 3] = q.w;
    }
    float r[4];
#pragma unroll
    for (int h = 0; h < 4; h++) {
        const float* vv = sve + h * 16;
        float s = bev;
#pragma unroll
        for (int k = 0; k < 16; k++) s += vv[k] * av[k];
        r[h] = s;
    }
    ((float4*)g_ae)[e] = make_float4(r[0], r[1], r[2], r[3]);
    atomicAdd(&g_deg[ei[EE + e]], 1);
}

// ---------------------------------------------------------------
// K3: single-block exclusive scan of degrees -> offsets + cursors
__global__ __launch_bounds__(1024) void k_scan() {
    __shared__ int s[1024];
    int t = threadIdx.x;
    const int CH = (NN + 1023) / 1024;   // 49
    int base = t * CH;
    int sum = 0;
    for (int i = 0; i < CH; i++) {
        int idx = base + i;
        sum += (idx < NN) ? g_deg[idx] : 0;
    }
    s[t] = sum;
    __syncthreads();
    for (int d = 1; d < 1024; d <<= 1) {
        int v = (t >= d) ? s[t - d] : 0;
        __syncthreads();
        s[t] += v;
        __syncthreads();
    }
    if (t == 1023) g_off[NN] = s[1023];
    int run = s[t] - sum;   // exclusive prefix
    for (int i = 0; i < CH; i++) {
        int idx = base + i;
        if (idx < NN) {
            g_off[idx] = run;
            g_cur[idx] = run;
            run += g_deg[idx];
        }
    }
}

// ---------------------------------------------------------------
// K4: scatter edges into CSR order; fold a_s[src]+a_e into the record
__global__ __launch_bounds__(256) void k_scatter(const int* __restrict__ ei) {
    int e = blockIdx.x * blockDim.x + threadIdx.x;
    if (e >= EE) return;
    int dst = ei[EE + e];
    int pos = atomicAdd(&g_cur[dst], 1);
    int src = ei[e];
    g_srcs[pos] = src;
    float4 a = ((const float4*)g_ae)[e];
    float4 b = ((const float4*)g_as)[src];
    ((float4*)g_ab)[pos] = make_float4(a.x + b.x, a.y + b.y, a.z + b.z, a.w + b.w);
}

// ---------------------------------------------------------------
// K5: one warp per destination node; inline softmax + weighted gather-sum.
// lane l accumulates out cols [4l,4l+4); head = l>>3. No atomics anywhere.
__global__ __launch_bounds__(256) void k_aggr(float* __restrict__ out) {
    int wid  = (blockIdx.x * blockDim.x + threadIdx.x) >> 5;
    int lane = threadIdx.x & 31;
    if (wid >= NN) return;
    int n = wid;
    int beg = g_off[n], end = g_off[n + 1];
    float atv = (lane < 4) ? g_at[n * 4 + lane] : 0.f;
    int h = lane >> 3;

    float4 acc = make_float4(0.f, 0.f, 0.f, 0.f);
    float sw = 0.f;
    for (int p = beg; p < end; p++) {
        float wv = 0.f;
        if (lane < 4) {
            float al = g_ab[p * 4 + lane] + atv;
            al = (al >= 0.f) ? al : 0.2f * al;
            wv = __expf(al);
            sw += wv;
        }
        float wgt = __shfl_sync(0xffffffffu, wv, h);
        int s = g_srcs[p];
        float4 xv = ((const float4*)g_xp)[s * 32 + lane];
        acc.x += wgt * xv.x; acc.y += wgt * xv.y;
        acc.z += wgt * xv.z; acc.w += wgt * xv.w;
    }
    float inv = (lane < 4 && sw > 0.f) ? (1.f / sw) : 0.f;
    float r = __shfl_sync(0xffffffffu, inv, h);
    float4* o4 = (float4*)out + n * 32 + lane;
    float4 ov = *o4;                      // residual + bias written by K1
    ov.x += r * acc.x; ov.y += r * acc.y;
    ov.z += r * acc.z; ov.w += r * acc.w;
    *o4 = ov;
}

// ---------------------------------------------------------------
extern "C" void kernel_launch(void* const* d_in, const int* in_sizes, int n_in,
                              void* d_out, int out_size) {
    const float* x      = (const float*)d_in[0];
    const int*   ei     = (const int*)  d_in[1];
    const float* ea     = (const float*)d_in[2];
    const float* W_lin  = (const float*)d_in[3];
    const float* w_s    = (const float*)d_in[4];
    const float* b_s    = (const float*)d_in[5];
    const float* w_t    = (const float*)d_in[6];
    const float* b_t    = (const float*)d_in[7];
    const float* W_edge = (const float*)d_in[8];
    const float* w_e    = (const float*)d_in[9];
    const float* b_e    = (const float*)d_in[10];
    const float* W_res  = (const float*)d_in[11];
    const float* bias   = (const float*)d_in[12];
    float* out = (float*)d_out;

    k_fold<<<1, 64>>>(W_edge, w_e);
    k_zero<<<(NN + 255) / 256, 256>>>();
    k_node<<<1184, 256>>>(x, W_lin, W_res, bias, w_s, b_s, w_t, b_t, out);
    k_edge<<<EE / 256, 256>>>(ea, ei, b_e);
    k_scan<<<1, 1024>>>();
    k_scatter<<<EE / 256, 256>>>(ei);
    k_aggr<<<(NN * 32) / 256, 256>>>(out);
}

// round 2
// speedup vs baseline: 1.4010x; 1.4010x over previous
#include <cuda_runtime.h>
#include <cuda_fp16.h>

#define NN 50000
#define EE 1600000

// ---- scratch ----
__device__ uint2  g_xp2[NN * 32];        // node projections fp16 [N,128] (4 halfs / uint2)
__device__ float  g_as[NN * 4];          // per-node source attn scalar
__device__ float  g_at[NN * 4];          // per-node target attn scalar
__device__ float4 g_rec[2 * EE];         // CSR records: [w0..w3][srcf,pad..] 32B/edge
__device__ int    g_deg[NN];
__device__ int    g_off[NN + 1];
__device__ int    g_cur[NN];
__device__ float  g_ve[64];              // folded edge vectors v_e[h][k]

__device__ __forceinline__ unsigned long long pack2f(float a, float b) {
    unsigned long long r;
    asm("mov.b64 %0, {%1, %2};" : "=l"(r) : "f"(a), "f"(b));
    return r;
}
__device__ __forceinline__ void unpack2f(unsigned long long v, float& a, float& b) {
    asm("mov.b64 {%0, %1}, %2;" : "=f"(a), "=f"(b) : "l"(v));
}
__device__ __forceinline__ unsigned long long fma2f(unsigned long long a,
                                                    unsigned long long b,
                                                    unsigned long long c) {
    unsigned long long r;
    asm("fma.rn.f32x2 %0, %1, %2, %3;" : "=l"(r) : "l"(a), "l"(b), "l"(c));
    return r;
}

// ---------------------------------------------------------------
// K0: zero degree histogram + fold W_edge with w_e
__global__ void k_init(const float* __restrict__ W_edge,
                       const float* __restrict__ w_e) {
    int i = blockIdx.x * blockDim.x + threadIdx.x;
    if (i < NN) g_deg[i] = 0;
    if (blockIdx.x == 0 && threadIdx.x < 64) {
        int h = threadIdx.x >> 4, k = threadIdx.x & 15;
        float s = 0.f;
#pragma unroll
        for (int f = 0; f < 32; f++) s += w_e[f] * W_edge[(h * 32 + f) * 16 + k];
        g_ve[threadIdx.x] = s;
    }
}

// ---------------------------------------------------------------
// K1: node projections, tiled 16 nodes/block-iteration, f32x2 FMA.
// t<128: xp col t (x@W_lin^T); t>=128: residual col (x@W_res^T + bias) -> out.
__global__ __launch_bounds__(256) void k_node(
    const float* __restrict__ x,
    const float* __restrict__ W_lin, const float* __restrict__ W_res,
    const float* __restrict__ bias,
    const float* __restrict__ w_s, const float* __restrict__ b_s,
    const float* __restrict__ w_t, const float* __restrict__ b_t,
    float* __restrict__ out) {
    __shared__ float sx[16 * 64];        // 4KB node tile
    __shared__ float sxp[16 * 132];      // padded xp tile (row i*132 + h*33 + f)
    __shared__ float sws[32], swt[32];

    int t = threadIdx.x;
    unsigned long long w2[32];
    {
        const float4* Wrow = (t < 128) ? ((const float4*)W_lin + t * 16)
                                       : ((const float4*)W_res + (t - 128) * 16);
#pragma unroll
        for (int k = 0; k < 16; k++) {
            float4 v = Wrow[k];
            w2[2 * k]     = pack2f(v.x, v.y);
            w2[2 * k + 1] = pack2f(v.z, v.w);
        }
    }
    float bval = (t >= 128) ? bias[t - 128] : 0.f;
    if (t < 32) sws[t] = w_s[t];
    else if (t < 64) swt[t - 32] = w_t[t - 32];
    float bsv = b_s[0], btv = b_t[0];

    int th = t >> 5, tf = t & 31;        // for xp writes: head col split

    for (int tile = blockIdx.x; tile < NN / 16; tile += gridDim.x) {
        int n0 = tile * 16;
        __syncthreads();
        ((float4*)sx)[(t >> 4) * 16 + (t & 15)] =
            ((const float4*)x)[(n0 + (t >> 4)) * 16 + (t & 15)];
        __syncthreads();
#pragma unroll 1
        for (int i = 0; i < 16; i++) {
            const ulonglong2* xr = (const ulonglong2*)(sx + i * 64);
            unsigned long long a0 = 0ull, a1 = 0ull;
#pragma unroll
            for (int k = 0; k < 16; k++) {
                ulonglong2 xv = xr[k];
                a0 = fma2f(w2[2 * k],     xv.x, a0);
                a1 = fma2f(w2[2 * k + 1], xv.y, a1);
            }
            float l0, h0, l1, h1;
            unpack2f(a0, l0, h0);
            unpack2f(a1, l1, h1);
            float acc = (l0 + l1) + (h0 + h1);
            if (t < 128) {
                sxp[i * 132 + th * 33 + tf] = acc;
                ((__half*)g_xp2)[(n0 + i) * 128 + t] = __float2half(acc);
            } else {
                out[(n0 + i) * 128 + (t - 128)] = acc + bval;
            }
        }
        __syncthreads();
        if (t < 128) {
            int i = t >> 3, task = t & 7, h = task & 3;
            const float* wv  = (task < 4) ? sws : swt;
            const float* xpr = sxp + i * 132 + h * 33;
            float s = 0.f;
#pragma unroll
            for (int f = 0; f < 32; f++) s += xpr[f] * wv[f];
            if (task < 4) g_as[(n0 + i) * 4 + h] = s + bsv;
            else          g_at[(n0 + i) * 4 + h] = s + btv;
        }
    }
}

// ---------------------------------------------------------------
// K2: degree histogram over destinations
__global__ __launch_bounds__(256) void k_deg(const int* __restrict__ ei) {
    int e = blockIdx.x * blockDim.x + threadIdx.x;
    if (e < EE) atomicAdd(&g_deg[ei[EE + e]], 1);
}

// ---------------------------------------------------------------
// K3: single-block exclusive scan -> offsets + cursors
__global__ __launch_bounds__(1024) void k_scan() {
    __shared__ int s[1024];
    int t = threadIdx.x;
    const int CH = (NN + 1023) / 1024;   // 49
    int base = t * CH;
    int sum = 0;
    for (int i = 0; i < CH; i++) {
        int idx = base + i;
        sum += (idx < NN) ? g_deg[idx] : 0;
    }
    s[t] = sum;
    __syncthreads();
    for (int d = 1; d < 1024; d <<= 1) {
        int v = (t >= d) ? s[t - d] : 0;
        __syncthreads();
        s[t] += v;
        __syncthreads();
    }
    if (t == 1023) g_off[NN] = s[1023];
    int run = s[t] - sum;
    for (int i = 0; i < CH; i++) {
        int idx = base + i;
        if (idx < NN) {
            g_off[idx] = run;
            g_cur[idx] = run;
            run += g_deg[idx];
        }
    }
}

// ---------------------------------------------------------------
// K4: fused edge pass — compute a_e inline, full alpha, leaky, exp,
//     scatter 32B packed record [w0..w3, srcf] to CSR position.
__global__ __launch_bounds__(256) void k_scatter(
    const float* __restrict__ ea, const int* __restrict__ ei,
    const float* __restrict__ b_e) {
    __shared__ float sve[64];
    if (threadIdx.x < 64) sve[threadIdx.x] = g_ve[threadIdx.x];
    __syncthreads();
    int e = blockIdx.x * blockDim.x + threadIdx.x;
    if (e >= EE) return;
    float bev = b_e[0];

    float av[16];
    const float4* p = (const float4*)ea + e * 4;
#pragma unroll
    for (int i = 0; i < 4; i++) {
        float4 q = p[i];
        av[4 * i] = q.x; av[4 * i + 1] = q.y;
        av[4 * i + 2] = q.z; av[4 * i + 3] = q.w;
    }
    int src = ei[e], dst = ei[EE + e];
    float4 as4 = ((const float4*)g_as)[src];
    float4 at4 = ((const float4*)g_at)[dst];
    float ash[4] = {as4.x, as4.y, as4.z, as4.w};
    float ath[4] = {at4.x, at4.y, at4.z, at4.w};

    float w[4];
#pragma unroll
    for (int h = 0; h < 4; h++) {
        const float* vv = sve + h * 16;
        float s = bev + ash[h] + ath[h];
#pragma unroll
        for (int k = 0; k < 16; k++) s += vv[k] * av[k];
        s = (s >= 0.f) ? s : 0.2f * s;
        w[h] = __expf(s);
    }
    int pos = atomicAdd(&g_cur[dst], 1);
    float* rp = (float*)(g_rec + 2 * pos);
    *(float4*)rp = make_float4(w[0], w[1], w[2], w[3]);
    rp[4] = __int_as_float(src);
}

// ---------------------------------------------------------------
// K5: one warp per destination node. lane l: head h=l>>3, cols 4l..4l+3.
// Records pre-exp'd -> loop is load + FFMA only. Chunk-4 for MLP.
__global__ __launch_bounds__(256) void k_aggr(float* __restrict__ out) {
    int wid = (blockIdx.x * blockDim.x + threadIdx.x) >> 5;
    if (wid >= NN) return;
    int lane = threadIdx.x & 31;
    int h = lane >> 3;
    int beg = g_off[wid], end = g_off[wid + 1];
    const float* recf = (const float*)g_rec;

    float4 acc = make_float4(0.f, 0.f, 0.f, 0.f);
    float sw = 0.f;
    int p = beg;
    for (; p + 4 <= end; p += 4) {
        float4 w4[4]; int s[4];
#pragma unroll
        for (int j = 0; j < 4; j++) {
            w4[j] = *(const float4*)(recf + 8 * (p + j));
            s[j]  = __float_as_int(recf[8 * (p + j) + 4]);
        }
        uint2 xv[4];
#pragma unroll
        for (int j = 0; j < 4; j++) xv[j] = g_xp2[s[j] * 32 + lane];
#pragma unroll
        for (int j = 0; j < 4; j++) {
            float wlo = (h & 1) ? w4[j].y : w4[j].x;
            float whi = (h & 1) ? w4[j].w : w4[j].z;
            float w   = (h & 2) ? whi : wlo;
            float2 fa = __half22float2(*(const half2*)&xv[j].x);
            float2 fb = __half22float2(*(const half2*)&xv[j].y);
            acc.x += w * fa.x; acc.y += w * fa.y;
            acc.z += w * fb.x; acc.w += w * fb.y;
            sw += w;
        }
    }
    for (; p < end; p++) {
        float4 w4 = *(const float4*)(recf + 8 * p);
        int s = __float_as_int(recf[8 * p + 4]);
        float wlo = (h & 1) ? w4.y : w4.x;
        float whi = (h & 1) ? w4.w : w4.z;
        float w   = (h & 2) ? whi : wlo;
        uint2 xv = g_xp2[s * 32 + lane];
        float2 fa = __half22float2(*(const half2*)&xv.x);
        float2 fb = __half22float2(*(const half2*)&xv.y);
        acc.x += w * fa.x; acc.y += w * fa.y;
        acc.z += w * fb.x; acc.w += w * fb.y;
        sw += w;
    }
    float inv = (sw > 0.f) ? (1.f / sw) : 0.f;
    float4* o4 = (float4*)out + wid * 32 + lane;
    float4 ov = *o4;                      // residual + bias from K1
    ov.x += inv * acc.x; ov.y += inv * acc.y;
    ov.z += inv * acc.z; ov.w += inv * acc.w;
    *o4 = ov;
}

// ---------------------------------------------------------------
extern "C" void kernel_launch(void* const* d_in, const int* in_sizes, int n_in,
                              void* d_out, int out_size) {
    const float* x      = (const float*)d_in[0];
    const int*   ei     = (const int*)  d_in[1];
    const float* ea     = (const float*)d_in[2];
    const float* W_lin  = (const float*)d_in[3];
    const float* w_s    = (const float*)d_in[4];
    const float* b_s    = (const float*)d_in[5];
    const float* w_t    = (const float*)d_in[6];
    const float* b_t    = (const float*)d_in[7];
    const float* W_edge = (const float*)d_in[8];
    const float* w_e    = (const float*)d_in[9];
    const float* b_e    = (const float*)d_in[10];
    const float* W_res  = (const float*)d_in[11];
    const float* bias   = (const float*)d_in[12];
    float* out = (float*)d_out;

    k_init<<<(NN + 255) / 256, 256>>>(W_edge, w_e);
    k_node<<<600, 256>>>(x, W_lin, W_res, bias, w_s, b_s, w_t, b_t, out);
    k_deg<<<EE / 256, 256>>>(ei);
    k_scan<<<1, 1024>>>();
    k_scatter<<<EE / 256, 256>>>(ea, ei, b_e);
    k_aggr<<<(NN * 32) / 256, 256>>>(out);
}

// round 3
// speedup vs baseline: 2.0232x; 1.4441x over previous
#include <cuda_runtime.h>
#include <cuda_fp16.h>

#define NN 50000
#define EE 1600000
#define SCB 196          // ceil(NN/256) scan blocks

// ---- scratch ----
__device__ uint2  g_xp2[NN * 32];        // node projections fp16 [N,128]
__device__ float  g_as[NN * 4];
__device__ float  g_at[NN * 4];
__device__ float4 g_w4[EE];              // CSR: exp'd weights per edge (4 heads)
__device__ int    g_srci[EE];            // CSR: source ids
__device__ int    g_deg[NN];
__device__ int    g_off[NN + 1];
__device__ int    g_cur[NN];
__device__ int    g_bsum[SCB];
__device__ float  g_ve[64];

__device__ __forceinline__ unsigned long long pack2f(float a, float b) {
    unsigned long long r;
    asm("mov.b64 %0, {%1, %2};" : "=l"(r) : "f"(a), "f"(b));
    return r;
}
__device__ __forceinline__ void unpack2f(unsigned long long v, float& a, float& b) {
    asm("mov.b64 {%0, %1}, %2;" : "=f"(a), "=f"(b) : "l"(v));
}
__device__ __forceinline__ unsigned long long fma2f(unsigned long long a,
                                                    unsigned long long b,
                                                    unsigned long long c) {
    unsigned long long r;
    asm("fma.rn.f32x2 %0, %1, %2, %3;" : "=l"(r) : "l"(a), "l"(b), "l"(c));
    return r;
}

// ---------------------------------------------------------------
__global__ void k_init(const float* __restrict__ W_edge,
                       const float* __restrict__ w_e) {
    int i = blockIdx.x * blockDim.x + threadIdx.x;
    if (i < NN) g_deg[i] = 0;
    if (blockIdx.x == 0 && threadIdx.x < 64) {
        int h = threadIdx.x >> 4, k = threadIdx.x & 15;
        float s = 0.f;
#pragma unroll
        for (int f = 0; f < 32; f++) s += w_e[f] * W_edge[(h * 32 + f) * 16 + k];
        g_ve[threadIdx.x] = s;
    }
}

// ---------------------------------------------------------------
// K1: node projections, 16 nodes/tile, f32x2 FMA.
__global__ __launch_bounds__(256) void k_node(
    const float* __restrict__ x,
    const float* __restrict__ W_lin, const float* __restrict__ W_res,
    const float* __restrict__ bias,
    const float* __restrict__ w_s, const float* __restrict__ b_s,
    const float* __restrict__ w_t, const float* __restrict__ b_t,
    float* __restrict__ out) {
    __shared__ float sx[16 * 64];
    __shared__ float sxp[16 * 132];
    __shared__ float sws[32], swt[32];

    int t = threadIdx.x;
    unsigned long long w2[32];
    {
        const float4* Wrow = (t < 128) ? ((const float4*)W_lin + t * 16)
                                       : ((const float4*)W_res + (t - 128) * 16);
#pragma unroll
        for (int k = 0; k < 16; k++) {
            float4 v = Wrow[k];
            w2[2 * k]     = pack2f(v.x, v.y);
            w2[2 * k + 1] = pack2f(v.z, v.w);
        }
    }
    float bval = (t >= 128) ? bias[t - 128] : 0.f;
    if (t < 32) sws[t] = w_s[t];
    else if (t < 64) swt[t - 32] = w_t[t - 32];
    float bsv = b_s[0], btv = b_t[0];
    int th = t >> 5, tf = t & 31;

    for (int tile = blockIdx.x; tile < NN / 16; tile += gridDim.x) {
        int n0 = tile * 16;
        __syncthreads();
        ((float4*)sx)[(t >> 4) * 16 + (t & 15)] =
            ((const float4*)x)[(n0 + (t >> 4)) * 16 + (t & 15)];
        __syncthreads();
#pragma unroll 1
        for (int i = 0; i < 16; i++) {
            const ulonglong2* xr = (const ulonglong2*)(sx + i * 64);
            unsigned long long a0 = 0ull, a1 = 0ull;
#pragma unroll
            for (int k = 0; k < 16; k++) {
                ulonglong2 xv = xr[k];
                a0 = fma2f(w2[2 * k],     xv.x, a0);
                a1 = fma2f(w2[2 * k + 1], xv.y, a1);
            }
            float l0, h0, l1, h1;
            unpack2f(a0, l0, h0);
            unpack2f(a1, l1, h1);
            float acc = (l0 + l1) + (h0 + h1);
            if (t < 128) {
                sxp[i * 132 + th * 33 + tf] = acc;
                ((__half*)g_xp2)[(n0 + i) * 128 + t] = __float2half(acc);
            } else {
                out[(n0 + i) * 128 + (t - 128)] = acc + bval;
            }
        }
        __syncthreads();
        if (t < 128) {
            int i = t >> 3, task = t & 7, h = task & 3;
            const float* wv  = (task < 4) ? sws : swt;
            const float* xpr = sxp + i * 132 + h * 33;
            float s = 0.f;
#pragma unroll
            for (int f = 0; f < 32; f++) s += xpr[f] * wv[f];
            if (task < 4) g_as[(n0 + i) * 4 + h] = s + bsv;
            else          g_at[(n0 + i) * 4 + h] = s + btv;
        }
    }
}

// ---------------------------------------------------------------
__global__ __launch_bounds__(256) void k_deg(const int* __restrict__ ei) {
    int e = blockIdx.x * blockDim.x + threadIdx.x;
    if (e < EE) atomicAdd(&g_deg[ei[EE + e]], 1);
}

// ---------------------------------------------------------------
// K3a: per-block sums of degrees
__global__ __launch_bounds__(256) void k_scan1() {
    __shared__ int s[8];
    int t = threadIdx.x;
    int idx = blockIdx.x * 256 + t;
    int d = (idx < NN) ? g_deg[idx] : 0;
    int v = d;
#pragma unroll
    for (int o = 16; o > 0; o >>= 1) v += __shfl_down_sync(0xffffffffu, v, o);
    if ((t & 31) == 0) s[t >> 5] = v;
    __syncthreads();
    if (t == 0) {
        int sum = 0;
#pragma unroll
        for (int i = 0; i < 8; i++) sum += s[i];
        g_bsum[blockIdx.x] = sum;
    }
}

// K3b: exclusive scan of 196 block sums (1 block)
__global__ __launch_bounds__(256) void k_scan2() {
    __shared__ int s[256];
    int t = threadIdx.x;
    int v = (t < SCB) ? g_bsum[t] : 0;
    s[t] = v;
    __syncthreads();
#pragma unroll
    for (int d = 1; d < 256; d <<= 1) {
        int u = (t >= d) ? s[t - d] : 0;
        __syncthreads();
        s[t] += u;
        __syncthreads();
    }
    if (t < SCB) g_bsum[t] = s[t] - v;   // exclusive
}

// K3c: block-local exclusive scan + base -> offsets & cursors
__global__ __launch_bounds__(256) void k_scan3() {
    __shared__ int s[256];
    int t = threadIdx.x;
    int idx = blockIdx.x * 256 + t;
    int d = (idx < NN) ? g_deg[idx] : 0;
    s[t] = d;
    __syncthreads();
#pragma unroll
    for (int dd = 1; dd < 256; dd <<= 1) {
        int u = (t >= dd) ? s[t - dd] : 0;
        __syncthreads();
        s[t] += u;
        __syncthreads();
    }
    int base = g_bsum[blockIdx.x];
    if (idx < NN) {
        int off = base + s[t] - d;       // exclusive
        g_off[idx] = off;
        g_cur[idx] = off;
        if (idx == NN - 1) g_off[NN] = off + d;
    }
}

// ---------------------------------------------------------------
// K4: fused edge pass: alpha -> leaky -> exp, scatter to CSR slot.
__global__ __launch_bounds__(256) void k_scatter(
    const float* __restrict__ ea, const int* __restrict__ ei,
    const float* __restrict__ b_e) {
    __shared__ float sve[64];
    if (threadIdx.x < 64) sve[threadIdx.x] = g_ve[threadIdx.x];
    __syncthreads();
    int e = blockIdx.x * blockDim.x + threadIdx.x;
    if (e >= EE) return;
    float bev = b_e[0];

    float av[16];
    const float4* p = (const float4*)ea + e * 4;
#pragma unroll
    for (int i = 0; i < 4; i++) {
        float4 q = p[i];
        av[4 * i] = q.x; av[4 * i + 1] = q.y;
        av[4 * i + 2] = q.z; av[4 * i + 3] = q.w;
    }
    int src = ei[e], dst = ei[EE + e];
    float4 as4 = ((const float4*)g_as)[src];
    float4 at4 = ((const float4*)g_at)[dst];
    float ash[4] = {as4.x, as4.y, as4.z, as4.w};
    float ath[4] = {at4.x, at4.y, at4.z, at4.w};

    float w[4];
#pragma unroll
    for (int h = 0; h < 4; h++) {
        const float* vv = sve + h * 16;
        float s = bev + ash[h] + ath[h];
#pragma unroll
        for (int k = 0; k < 16; k++) s += vv[k] * av[k];
        s = (s >= 0.f) ? s : 0.2f * s;
        w[h] = __expf(s);
    }
    int pos = atomicAdd(&g_cur[dst], 1);
    g_w4[pos] = make_float4(w[0], w[1], w[2], w[3]);
    g_srci[pos] = src;
}

// ---------------------------------------------------------------
// K5: one warp per destination node; pre-exp'd weights, pure FFMA loop.
__global__ __launch_bounds__(256) void k_aggr(float* __restrict__ out) {
    int wid = (blockIdx.x * blockDim.x + threadIdx.x) >> 5;
    if (wid >= NN) return;
    int lane = threadIdx.x & 31;
    int h = lane >> 3;
    int beg = g_off[wid], end = g_off[wid + 1];

    float4 acc = make_float4(0.f, 0.f, 0.f, 0.f);
    float sw = 0.f;
    int p = beg;
    for (; p + 4 <= end; p += 4) {
        float4 w4[4]; int s[4];
#pragma unroll
        for (int j = 0; j < 4; j++) { w4[j] = g_w4[p + j]; s[j] = g_srci[p + j]; }
        uint2 xv[4];
#pragma unroll
        for (int j = 0; j < 4; j++) xv[j] = g_xp2[s[j] * 32 + lane];
#pragma unroll
        for (int j = 0; j < 4; j++) {
            float wlo = (h & 1) ? w4[j].y : w4[j].x;
            float whi = (h & 1) ? w4[j].w : w4[j].z;
            float w   = (h & 2) ? whi : wlo;
            float2 fa = __half22float2(*(const half2*)&xv[j].x);
            float2 fb = __half22float2(*(const half2*)&xv[j].y);
            acc.x += w * fa.x; acc.y += w * fa.y;
            acc.z += w * fb.x; acc.w += w * fb.y;
            sw += w;
        }
    }
    for (; p < end; p++) {
        float4 w4 = g_w4[p];
        int s = g_srci[p];
        float wlo = (h & 1) ? w4.y : w4.x;
        float whi = (h & 1) ? w4.w : w4.z;
        float w   = (h & 2) ? whi : wlo;
        uint2 xv = g_xp2[s * 32 + lane];
        float2 fa = __half22float2(*(const half2*)&xv.x);
        float2 fb = __half22float2(*(const half2*)&xv.y);
        acc.x += w * fa.x; acc.y += w * fa.y;
        acc.z += w * fb.x; acc.w += w * fb.y;
        sw += w;
    }
    float inv = (sw > 0.f) ? (1.f / sw) : 0.f;
    float4* o4 = (float4*)out + wid * 32 + lane;
    float4 ov = *o4;
    ov.x += inv * acc.x; ov.y += inv * acc.y;
    ov.z += inv * acc.z; ov.w += inv * acc.w;
    *o4 = ov;
}

// ---------------------------------------------------------------
extern "C" void kernel_launch(void* const* d_in, const int* in_sizes, int n_in,
                              void* d_out, int out_size) {
    const float* x      = (const float*)d_in[0];
    const int*   ei     = (const int*)  d_in[1];
    const float* ea     = (const float*)d_in[2];
    const float* W_lin  = (const float*)d_in[3];
    const float* w_s    = (const float*)d_in[4];
    const float* b_s    = (const float*)d_in[5];
    const float* w_t    = (const float*)d_in[6];
    const float* b_t    = (const float*)d_in[7];
    const float* W_edge = (const float*)d_in[8];
    const float* w_e    = (const float*)d_in[9];
    const float* b_e    = (const float*)d_in[10];
    const float* W_res  = (const float*)d_in[11];
    const float* bias   = (const float*)d_in[12];
    float* out = (float*)d_out;

    k_init<<<(NN + 255) / 256, 256>>>(W_edge, w_e);
    k_node<<<600, 256>>>(x, W_lin, W_res, bias, w_s, b_s, w_t, b_t, out);
    k_deg<<<EE / 256, 256>>>(ei);
    k_scan1<<<SCB, 256>>>();
    k_scan2<<<1, 256>>>();
    k_scan3<<<SCB, 256>>>();
    k_scatter<<<EE / 256, 256>>>(ea, ei, b_e);
    k_aggr<<<(NN * 32) / 256, 256>>>(out);
}

// round 4
// speedup vs baseline: 2.2453x; 1.1098x over previous
#include <cuda_runtime.h>
#include <cuda_fp16.h>

#define NN 50000
#define EE 1600000
#define SCB 196          // ceil(NN/256) scan blocks
#define NODE_BLKS 600
#define DEG_BLKS  1024

// ---- scratch ----
__device__ uint2  g_xp2[NN * 32];        // node projections fp16 [N,128]
__device__ float  g_as[NN * 4];
__device__ float  g_at[NN * 4];
__device__ uint4  g_rec[EE];             // CSR: {w01h2, w23h2, src, pad}
__device__ int    g_deg[NN];
__device__ int    g_off[NN + 1];
__device__ int    g_cur[NN];
__device__ int    g_bsum[SCB];
__device__ float  g_ve[64];

__device__ __forceinline__ unsigned long long pack2f(float a, float b) {
    unsigned long long r;
    asm("mov.b64 %0, {%1, %2};" : "=l"(r) : "f"(a), "f"(b));
    return r;
}
__device__ __forceinline__ void unpack2f(unsigned long long v, float& a, float& b) {
    asm("mov.b64 {%0, %1}, %2;" : "=f"(a), "=f"(b) : "l"(v));
}
__device__ __forceinline__ unsigned long long fma2f(unsigned long long a,
                                                    unsigned long long b,
                                                    unsigned long long c) {
    unsigned long long r;
    asm("fma.rn.f32x2 %0, %1, %2, %3;" : "=l"(r) : "l"(a), "l"(b), "l"(c));
    return r;
}

// ---------------------------------------------------------------
// K0: zero degree histogram + fold W_edge with w_e
__global__ void k_init(const float* __restrict__ W_edge,
                       const float* __restrict__ w_e) {
    int i = blockIdx.x * blockDim.x + threadIdx.x;
    if (i < NN) g_deg[i] = 0;
    if (blockIdx.x == 0 && threadIdx.x < 64) {
        int h = threadIdx.x >> 4, k = threadIdx.x & 15;
        float s = 0.f;
#pragma unroll
        for (int f = 0; f < 32; f++) s += w_e[f] * W_edge[(h * 32 + f) * 16 + k];
        g_ve[threadIdx.x] = s;
    }
}

// ---------------------------------------------------------------
// K1: FUSED node projections (blocks < NODE_BLKS) + dst-degree
//     histogram (remaining blocks, grid-stride). Deg work is pure
//     memory and hides under the compute-bound GEMM.
__global__ __launch_bounds__(256) void k_node(
    const float* __restrict__ x, const int* __restrict__ ei,
    const float* __restrict__ W_lin, const float* __restrict__ W_res,
    const float* __restrict__ bias,
    const float* __restrict__ w_s, const float* __restrict__ b_s,
    const float* __restrict__ w_t, const float* __restrict__ b_t,
    float* __restrict__ out) {
    if (blockIdx.x >= NODE_BLKS) {
        // ---- degree histogram path ----
        int nb = gridDim.x - NODE_BLKS;
        for (int e = (blockIdx.x - NODE_BLKS) * 256 + threadIdx.x; e < EE;
             e += nb * 256)
            atomicAdd(&g_deg[ei[EE + e]], 1);
        return;
    }
    __shared__ float sx[16 * 64];
    __shared__ float sxp[16 * 132];
    __shared__ float sws[32], swt[32];

    int t = threadIdx.x;
    unsigned long long w2[32];
    {
        const float4* Wrow = (t < 128) ? ((const float4*)W_lin + t * 16)
                                       : ((const float4*)W_res + (t - 128) * 16);
#pragma unroll
        for (int k = 0; k < 16; k++) {
            float4 v = Wrow[k];
            w2[2 * k]     = pack2f(v.x, v.y);
            w2[2 * k + 1] = pack2f(v.z, v.w);
        }
    }
    float bval = (t >= 128) ? bias[t - 128] : 0.f;
    if (t < 32) sws[t] = w_s[t];
    else if (t < 64) swt[t - 32] = w_t[t - 32];
    float bsv = b_s[0], btv = b_t[0];
    int th = t >> 5, tf = t & 31;

    for (int tile = blockIdx.x; tile < NN / 16; tile += NODE_BLKS) {
        int n0 = tile * 16;
        __syncthreads();
        ((float4*)sx)[(t >> 4) * 16 + (t & 15)] =
            ((const float4*)x)[(n0 + (t >> 4)) * 16 + (t & 15)];
        __syncthreads();
#pragma unroll 1
        for (int i = 0; i < 16; i++) {
            const ulonglong2* xr = (const ulonglong2*)(sx + i * 64);
            unsigned long long a0 = 0ull, a1 = 0ull;
#pragma unroll
            for (int k = 0; k < 16; k++) {
                ulonglong2 xv = xr[k];
                a0 = fma2f(w2[2 * k],     xv.x, a0);
                a1 = fma2f(w2[2 * k + 1], xv.y, a1);
            }
            float l0, h0, l1, h1;
            unpack2f(a0, l0, h0);
            unpack2f(a1, l1, h1);
            float acc = (l0 + l1) + (h0 + h1);
            if (t < 128) {
                sxp[i * 132 + th * 33 + tf] = acc;
                ((__half*)g_xp2)[(n0 + i) * 128 + t] = __float2half(acc);
            } else {
                out[(n0 + i) * 128 + (t - 128)] = acc + bval;
            }
        }
        __syncthreads();
        if (t < 128) {
            int i = t >> 3, task = t & 7, h = task & 3;
            const float* wv  = (task < 4) ? sws : swt;
            const float* xpr = sxp + i * 132 + h * 33;
            float s = 0.f;
#pragma unroll
            for (int f = 0; f < 32; f++) s += xpr[f] * wv[f];
            if (task < 4) g_as[(n0 + i) * 4 + h] = s + bsv;
            else          g_at[(n0 + i) * 4 + h] = s + btv;
        }
    }
}

// ---------------------------------------------------------------
// K3a: per-block degree sums
__global__ __launch_bounds__(256) void k_scan1() {
    __shared__ int s[8];
    int t = threadIdx.x;
    int idx = blockIdx.x * 256 + t;
    int v = (idx < NN) ? g_deg[idx] : 0;
#pragma unroll
    for (int o = 16; o > 0; o >>= 1) v += __shfl_down_sync(0xffffffffu, v, o);
    if ((t & 31) == 0) s[t >> 5] = v;
    __syncthreads();
    if (t == 0) {
        int sum = 0;
#pragma unroll
        for (int i = 0; i < 8; i++) sum += s[i];
        g_bsum[blockIdx.x] = sum;
    }
}

// K3b: exclusive scan of block sums
__global__ __launch_bounds__(256) void k_scan2() {
    __shared__ int s[256];
    int t = threadIdx.x;
    int v = (t < SCB) ? g_bsum[t] : 0;
    s[t] = v;
    __syncthreads();
#pragma unroll
    for (int d = 1; d < 256; d <<= 1) {
        int u = (t >= d) ? s[t - d] : 0;
        __syncthreads();
        s[t] += u;
        __syncthreads();
    }
    if (t < SCB) g_bsum[t] = s[t] - v;
}

// K3c: local scan + base -> offsets & cursors
__global__ __launch_bounds__(256) void k_scan3() {
    __shared__ int s[256];
    int t = threadIdx.x;
    int idx = blockIdx.x * 256 + t;
    int d = (idx < NN) ? g_deg[idx] : 0;
    s[t] = d;
    __syncthreads();
#pragma unroll
    for (int dd = 1; dd < 256; dd <<= 1) {
        int u = (t >= dd) ? s[t - dd] : 0;
        __syncthreads();
        s[t] += u;
        __syncthreads();
    }
    int base = g_bsum[blockIdx.x];
    if (idx < NN) {
        int off = base + s[t] - d;
        g_off[idx] = off;
        g_cur[idx] = off;
        if (idx == NN - 1) g_off[NN] = off + d;
    }
}

// ---------------------------------------------------------------
// K4: fused edge pass, 2 edges/thread from two coalesced streams.
//     alpha -> leaky -> exp -> fp16 pack -> one 16B uint4 scatter.
__global__ __launch_bounds__(256) void k_scatter(
    const float* __restrict__ ea, const int* __restrict__ ei,
    const float* __restrict__ b_e) {
    __shared__ float sve[64];
    if (threadIdx.x < 64) sve[threadIdx.x] = g_ve[threadIdx.x];
    __syncthreads();
    float bev = b_e[0];
    int gid = blockIdx.x * blockDim.x + threadIdx.x;
    const int HALF = EE / 2;
    if (gid >= HALF) return;

    int e0 = gid, e1 = gid + HALF;
    // batched loads for both edges
    float4 q0[4], q1[4];
    const float4* p0 = (const float4*)ea + e0 * 4;
    const float4* p1 = (const float4*)ea + e1 * 4;
#pragma unroll
    for (int i = 0; i < 4; i++) { q0[i] = p0[i]; q1[i] = p1[i]; }
    int s0 = ei[e0], d0 = ei[EE + e0];
    int s1 = ei[e1], d1 = ei[EE + e1];
    float4 as0 = ((const float4*)g_as)[s0];
    float4 at0 = ((const float4*)g_at)[d0];
    float4 as1 = ((const float4*)g_as)[s1];
    float4 at1 = ((const float4*)g_at)[d1];

#pragma unroll
    for (int pass = 0; pass < 2; pass++) {
        float4* q = pass ? q1 : q0;
        float4 as4 = pass ? as1 : as0;
        float4 at4 = pass ? at1 : at0;
        int src = pass ? s1 : s0;
        int dst = pass ? d1 : d0;
        float av[16];
#pragma unroll
        for (int i = 0; i < 4; i++) {
            av[4 * i] = q[i].x; av[4 * i + 1] = q[i].y;
            av[4 * i + 2] = q[i].z; av[4 * i + 3] = q[i].w;
        }
        float base[4] = {as4.x + at4.x, as4.y + at4.y,
                         as4.z + at4.z, as4.w + at4.w};
        float w[4];
#pragma unroll
        for (int h = 0; h < 4; h++) {
            const float* vv = sve + h * 16;
            float s = bev + base[h];
#pragma unroll
            for (int k = 0; k < 16; k++) s += vv[k] * av[k];
            s = (s >= 0.f) ? s : 0.2f * s;
            w[h] = __expf(s);
        }
        int pos = atomicAdd(&g_cur[dst], 1);
        uint4 rec;
        half2 w01 = __floats2half2_rn(w[0], w[1]);
        half2 w23 = __floats2half2_rn(w[2], w[3]);
        rec.x = *(unsigned*)&w01;
        rec.y = *(unsigned*)&w23;
        rec.z = (unsigned)src;
        rec.w = 0u;
        g_rec[pos] = rec;
    }
}

// ---------------------------------------------------------------
// K5: one warp per destination node; chunk-8 batched loads for MLP.
__global__ __launch_bounds__(256) void k_aggr(float* __restrict__ out) {
    int wid = (blockIdx.x * blockDim.x + threadIdx.x) >> 5;
    if (wid >= NN) return;
    int lane = threadIdx.x & 31;
    int h = lane >> 3;
    int beg = g_off[wid], end = g_off[wid + 1];

    float4 acc = make_float4(0.f, 0.f, 0.f, 0.f);
    float sw = 0.f;
    int p = beg;
    for (; p + 8 <= end; p += 8) {
        uint4 r[8];
#pragma unroll
        for (int j = 0; j < 8; j++) r[j] = g_rec[p + j];   // broadcast loads
        uint2 xv[8];
#pragma unroll
        for (int j = 0; j < 8; j++) xv[j] = g_xp2[r[j].z * 32 + lane];
#pragma unroll
        for (int j = 0; j < 8; j++) {
            unsigned wp = (h & 2) ? r[j].y : r[j].x;
            half2 hw = *(half2*)&wp;
            float w = (h & 1) ? __high2float(hw) : __low2float(hw);
            float2 fa = __half22float2(*(const half2*)&xv[j].x);
            float2 fb = __half22float2(*(const half2*)&xv[j].y);
            acc.x += w * fa.x; acc.y += w * fa.y;
            acc.z += w * fb.x; acc.w += w * fb.y;
            sw += w;
        }
    }
    for (; p < end; p++) {
        uint4 r = g_rec[p];
        unsigned wp = (h & 2) ? r.y : r.x;
        half2 hw = *(half2*)&wp;
        float w = (h & 1) ? __high2float(hw) : __low2float(hw);
        uint2 xv = g_xp2[r.z * 32 + lane];
        float2 fa = __half22float2(*(const half2*)&xv.x);
        float2 fb = __half22float2(*(const half2*)&xv.y);
        acc.x += w * fa.x; acc.y += w * fa.y;
        acc.z += w * fb.x; acc.w += w * fb.y;
        sw += w;
    }
    float inv = (sw > 0.f) ? (1.f / sw) : 0.f;
    float4* o4 = (float4*)out + wid * 32 + lane;
    float4 ov = *o4;
    ov.x += inv * acc.x; ov.y += inv * acc.y;
    ov.z += inv * acc.z; ov.w += inv * acc.w;
    *o4 = ov;
}

// ---------------------------------------------------------------
extern "C" void kernel_launch(void* const* d_in, const int* in_sizes, int n_in,
                              void* d_out, int out_size) {
    const float* x      = (const float*)d_in[0];
    const int*   ei     = (const int*)  d_in[1];
    const float* ea     = (const float*)d_in[2];
    const float* W_lin  = (const float*)d_in[3];
    const float* w_s    = (const float*)d_in[4];
    const float* b_s    = (const float*)d_in[5];
    const float* w_t    = (const float*)d_in[6];
    const float* b_t    = (const float*)d_in[7];
    const float* W_edge = (const float*)d_in[8];
    const float* w_e    = (const float*)d_in[9];
    const float* b_e    = (const float*)d_in[10];
    const float* W_res  = (const float*)d_in[11];
    const float* bias   = (const float*)d_in[12];
    float* out = (float*)d_out;

    k_init<<<(NN + 255) / 256, 256>>>(W_edge, w_e);
    k_node<<<NODE_BLKS + DEG_BLKS, 256>>>(x, ei, W_lin, W_res, bias,
                                          w_s, b_s, w_t, b_t, out);
    k_scan1<<<SCB, 256>>>();
    k_scan2<<<1, 256>>>();
    k_scan3<<<SCB, 256>>>();
    k_scatter<<<EE / 512, 256>>>(ea, ei, b_e);
    k_aggr<<<(NN * 32) / 256, 256>>>(out);
}